// round 4
// baseline (speedup 1.0000x reference)
#include <cuda_runtime.h>
#include <math.h>
#include <stdint.h>

// Problem dims
static constexpr int S_LEN = 512;
static constexpr int BATCH = 64;
static constexpr int IDIM  = 256;
static constexpr int HDIM  = 512;
static constexpr int EDIM  = 512;

// Persistent kernel config: 128 CTAs = 32 col-groups x 4 k-split (one cluster each)
static constexpr int G    = 128;
static constexpr int NT   = 128;   // 4 warps
static constexpr int CPB  = 16;    // columns per CTA (cg owns 16 cols; within cluster, rank ks owns 4)
static constexpr int NKS  = 4;     // k-split factor (cluster size)

// smem layout (in ull = 8B units)
static constexpr int ST_PITCH  = 36;    // ull per state row (32 data + 4 pad)
static constexpr int W_PITCH   = 20;    // floats per weight row (16 data + 4 pad)
static constexpr int RED_PITCH = 516;   // ull per ksub slab (512 + 4 stagger)
static constexpr int OFF_ST2 = 0;                    // 256*36      = 9216 ull
static constexpr int OFF_W1  = 256 * ST_PITCH;       // 128*20 fl   = 1280 ull
static constexpr int OFF_W2  = OFF_W1 + (128 * W_PITCH) / 2;  // 256*20 fl = 2560 ull
static constexpr int OFF_RED = OFF_W2 + (256 * W_PITCH) / 2;  // 8*516     = 4128 ull
static constexpr int SMEM_ULL   = OFF_RED + 8 * RED_PITCH;
static constexpr int SMEM_BYTES = SMEM_ULL * 8;      // 137,472 B

// Device scratch (allocation-free rule)
__device__ float g_xw[S_LEN * HDIM * BATCH];     // [t][c][b]  x@W_ih^T + b_ih + b_hh
__device__ float g_h[2][HDIM * BATCH];           // [c][b] column-major state, double buffered
__device__ float g_a[2][EDIM * BATCH];
__device__ float g_part[G * CPB * BATCH];        // per-CTA partial tiles [cta][c16][b64]
__device__ unsigned g_bar_count = 0;
__device__ unsigned g_bar_gen   = 0;

// ---------------------------------------------------------------------------
// f32x2 helpers (Blackwell packed fp32 — exact 2x FFMA)
// ---------------------------------------------------------------------------
typedef unsigned long long ull;

__device__ __forceinline__ ull packdup(float w) {
    ull r; unsigned u = __float_as_uint(w);
    asm("mov.b64 %0, {%1, %2};" : "=l"(r) : "r"(u), "r"(u));
    return r;
}
__device__ __forceinline__ ull fma2(ull a, ull b, ull c) {
    ull d; asm("fma.rn.f32x2 %0, %1, %2, %3;" : "=l"(d) : "l"(a), "l"(b), "l"(c));
    return d;
}
__device__ __forceinline__ ull add2(ull a, ull b) {
    ull d; asm("add.rn.f32x2 %0, %1, %2;" : "=l"(d) : "l"(a), "l"(b));
    return d;
}

// ---------------------------------------------------------------------------
// Precompute GEMM: g_xw[t][j][b] = sum_i x[b][t][i]*W_ih[j][i] + b_ih[j] + b_hh[j]
// ---------------------------------------------------------------------------
__global__ __launch_bounds__(256) void xw_gemm(const float* __restrict__ x,
                                               const float* __restrict__ W_ih,
                                               const float* __restrict__ b_ih,
                                               const float* __restrict__ b_hh) {
    __shared__ float As[16][68];
    __shared__ float Bs[16][68];

    const int r0 = blockIdx.x * 64;
    const int j0 = blockIdx.y * 64;
    const int tx = threadIdx.x & 15;
    const int ty = threadIdx.x >> 4;

    float acc[4][4] = {};

    for (int k0 = 0; k0 < IDIM; k0 += 16) {
#pragma unroll
        for (int m = 0; m < 4; ++m) {
            int lin = threadIdx.x + 256 * m;
            int rr = lin >> 4, kk = lin & 15;
            As[kk][rr] = x[(r0 + rr) * IDIM + k0 + kk];
            Bs[kk][rr] = W_ih[(j0 + rr) * IDIM + k0 + kk];
        }
        __syncthreads();
#pragma unroll
        for (int kk = 0; kk < 16; ++kk) {
            float4 av = *(const float4*)&As[kk][ty * 4];
            float4 bv = *(const float4*)&Bs[kk][tx * 4];
            float af[4] = {av.x, av.y, av.z, av.w};
            float bf[4] = {bv.x, bv.y, bv.z, bv.w};
#pragma unroll
            for (int i = 0; i < 4; ++i)
#pragma unroll
                for (int j = 0; j < 4; ++j)
                    acc[i][j] += af[i] * bf[j];
        }
        __syncthreads();
    }

#pragma unroll
    for (int i = 0; i < 4; ++i) {
        int r = r0 + ty * 4 + i;
        int t = r & (S_LEN - 1);
        int b = r >> 9;
#pragma unroll
        for (int j = 0; j < 4; ++j) {
            int col = j0 + tx * 4 + j;
            g_xw[(t * HDIM + col) * BATCH + b] = acc[i][j] + b_ih[col] + b_hh[col];
        }
    }
}

// ---------------------------------------------------------------------------
// Grid-wide sense barrier
// ---------------------------------------------------------------------------
__device__ __forceinline__ void grid_barrier() {
    __syncthreads();
    if (threadIdx.x == 0) {
        unsigned gen = *(volatile unsigned*)&g_bar_gen;
        __threadfence();
        unsigned a = atomicAdd(&g_bar_count, 1u);
        if (a == G - 1) {
            atomicExch(&g_bar_count, 0u);
            __threadfence();
            atomicAdd(&g_bar_gen, 1u);
        } else {
            while (*(volatile unsigned*)&g_bar_gen == gen) { }
        }
        __threadfence();
    }
    __syncthreads();
}

__device__ __forceinline__ void cluster_sync_() {
    asm volatile("barrier.cluster.arrive.aligned;" ::: "memory");
    asm volatile("barrier.cluster.wait.aligned;" ::: "memory");
}

// stage `rows` state rows (64 floats each, contiguous) into st2 with pitch
__device__ __forceinline__ void stage(ull* __restrict__ st2,
                                      const float* __restrict__ src, int rows) {
    const ulonglong2* s = (const ulonglong2*)src;
    for (int i = threadIdx.x; i < rows * 16; i += NT) {
        int r = i >> 4, q = i & 15;
        ((ulonglong2*)(st2 + r * ST_PITCH))[q] = s[i];
    }
}

// register-tiled GEMM slice: acc[c 8][bp 4] += h2[k][bp] * w[k][c], k in thread range
template <int KK>
__device__ __forceinline__ void gemm_tile(const ull* __restrict__ st2,
                                          const float* __restrict__ wT,
                                          int ksub, int cg2, int bg, ull acc[8][4]) {
    const int k0 = ksub * KK;
#pragma unroll 8
    for (int kk = 0; kk < KK; ++kk) {
        const int k = k0 + kk;
        const ulonglong2* hp = (const ulonglong2*)(st2 + k * ST_PITCH + bg * 4);
        ulonglong2 h01 = hp[0];
        ulonglong2 h23 = hp[1];
        ull hv[4] = {h01.x, h01.y, h23.x, h23.y};
        const float4* wp = (const float4*)(wT + k * W_PITCH + cg2 * 8);
        float4 wa = wp[0], wb = wp[1];
        float wf[8] = {wa.x, wa.y, wa.z, wa.w, wb.x, wb.y, wb.z, wb.w};
#pragma unroll
        for (int c = 0; c < 8; ++c) {
            ull wd = packdup(wf[c]);
#pragma unroll
            for (int bp = 0; bp < 4; ++bp) acc[c][bp] = fma2(hv[bp], wd, acc[c][bp]);
        }
    }
}

// intra-CTA 8-way k-reduction through smem, then STG the 64x16 partial tile
__device__ __forceinline__ void reduce_and_emit(ull* __restrict__ red, ull acc[8][4],
                                                int ksub, int cg2, int bg,
                                                int tid, int bid) {
#pragma unroll
    for (int c = 0; c < 8; ++c) {
        ull* dst = red + ksub * RED_PITCH + (cg2 * 8 + c) * 32 + bg * 4;
        ((ulonglong2*)dst)[0] = make_ulonglong2(acc[c][0], acc[c][1]);
        ((ulonglong2*)dst)[1] = make_ulonglong2(acc[c][2], acc[c][3]);
    }
    __syncthreads();
    ull s[4] = {0ull, 0ull, 0ull, 0ull};
#pragma unroll
    for (int k2 = 0; k2 < 8; ++k2) {
        const ulonglong2* src = (const ulonglong2*)(red + k2 * RED_PITCH + tid * 4);
        ulonglong2 a = src[0], b = src[1];
        s[0] = add2(s[0], a.x); s[1] = add2(s[1], a.y);
        s[2] = add2(s[2], b.x); s[3] = add2(s[3], b.y);
    }
    float* gp = g_part + bid * (CPB * BATCH) + (tid >> 3) * BATCH + (tid & 7) * 8;
    ((ulonglong2*)gp)[0] = make_ulonglong2(s[0], s[1]);
    ((ulonglong2*)gp)[1] = make_ulonglong2(s[2], s[3]);
}

// ---------------------------------------------------------------------------
// Persistent RNN kernel: G=128 CTAs, clusters of 4 (the k-splits of one cg)
// ---------------------------------------------------------------------------
__global__ __launch_bounds__(NT, 1) __cluster_dims__(NKS, 1, 1)
void rnn_persistent(const float* __restrict__ W_hh,
                    const float* __restrict__ W_ya,
                    const float* __restrict__ W_aa,
                    const float* __restrict__ b_ya,
                    const float* __restrict__ b_aa,
                    float* __restrict__ out) {
    extern __shared__ ull smem_u[];
    ull*   st2 = smem_u + OFF_ST2;
    float* wT1 = (float*)(smem_u + OFF_W1);
    float* wT2 = (float*)(smem_u + OFF_W2);
    ull*   red = smem_u + OFF_RED;

    const int tid = threadIdx.x;
    const int bid = blockIdx.x;
    const int cg  = bid >> 2;       // column group 0..31
    const int ks  = bid & 3;        // k-split rank (== cluster rank)

    // thread roles for the GEMM tile
    const int ksub = tid >> 4;          // 0..7  (intra-CTA k split)
    const int cg2  = (tid >> 3) & 1;    // 0..1  (8-col halves)
    const int bg   = tid & 7;           // 0..7  (4 batch-pairs each)

    // zero-init state buffers (deterministic per replay)
    for (int i = bid * NT + tid; i < HDIM * BATCH; i += G * NT) g_h[0][i] = 0.f;
    for (int i = bid * NT + tid; i < EDIM * BATCH; i += G * NT) g_a[0][i] = 0.f;

    // resident weight slices (transposed, padded)
    for (int i = tid; i < CPB * 128; i += NT) {
        int c = i >> 7, k = i & 127;
        wT1[k * W_PITCH + c] = W_hh[(cg * CPB + c) * HDIM + ks * 128 + k];
    }
    for (int i = tid; i < CPB * 256; i += NT) {
        int c = i >> 8, k = i & 255;
        int kg = (ks & 1) * 256 + k;
        wT2[k * W_PITCH + c] = (ks < 2) ? W_ya[(cg * CPB + c) * HDIM + kg]
                                        : W_aa[(cg * CPB + c) * EDIM + kg];
    }

    // owner-final role: this CTA finalizes global cols cg*16 + ks*4 .. +4
    const int ciA = tid >> 6;               // 0..1 ; second rep adds +2
    const int bF  = tid & 63;
    const int cA  = cg * CPB + ks * 4 + ciA;
    const int cB  = cA + 2;
    const float biasA = b_ya[cA] + b_aa[cA];
    const float biasB = b_ya[cB] + b_aa[cB];

    grid_barrier();

    int cur = 0;
    for (int t = 0; t < S_LEN; ++t) {
        const int nxt = cur ^ 1;

        // ===== phase 1: h_new = tanh(xw_t + h_old @ W_hh^T), k-split over cluster =====
        stage(st2, g_h[cur] + ks * 128 * BATCH, 128);
        __syncthreads();
        {
            ull acc[8][4] = {};
            gemm_tile<16>(st2, wT1, ksub, cg2, bg, acc);
            reduce_and_emit(red, acc, ksub, cg2, bg, tid, bid);
        }
        cluster_sync_();   // partials of the 4 k-splits now visible cluster-wide
        {
            const int base = (bid & ~3) * (CPB * BATCH);
            float vA = 0.f, vB = 0.f;
#pragma unroll
            for (int p = 0; p < NKS; ++p) {
                const float* pp = g_part + base + p * (CPB * BATCH);
                vA += pp[(ks * 4 + ciA) * BATCH + bF];
                vB += pp[(ks * 4 + ciA + 2) * BATCH + bF];
            }
            vA += g_xw[(t * HDIM + cA) * BATCH + bF];
            vB += g_xw[(t * HDIM + cB) * BATCH + bF];
            g_h[nxt][cA * BATCH + bF] = tanhf(vA);
            g_h[nxt][cB * BATCH + bF] = tanhf(vB);
        }
        grid_barrier();

        // ===== phase 2: a_new = tanh(h_new@W_ya^T + a_old@W_aa^T + bias), K=1024 split =====
        {
            const float* src2 = (ks < 2) ? (g_h[nxt] + ks * 256 * BATCH)
                                         : (g_a[cur] + (ks & 1) * 256 * BATCH);
            stage(st2, src2, 256);
        }
        __syncthreads();
        {
            ull acc[8][4] = {};
            gemm_tile<32>(st2, wT2, ksub, cg2, bg, acc);
            reduce_and_emit(red, acc, ksub, cg2, bg, tid, bid);
        }
        cluster_sync_();
        {
            const int base = (bid & ~3) * (CPB * BATCH);
            float vA = 0.f, vB = 0.f;
#pragma unroll
            for (int p = 0; p < NKS; ++p) {
                const float* pp = g_part + base + p * (CPB * BATCH);
                vA += pp[(ks * 4 + ciA) * BATCH + bF];
                vB += pp[(ks * 4 + ciA + 2) * BATCH + bF];
            }
            float aA = tanhf(vA + biasA);
            float aB = tanhf(vB + biasB);
            g_a[nxt][cA * BATCH + bF] = aA;
            g_a[nxt][cB * BATCH + bF] = aB;
            if (t == S_LEN - 1) {
                out[bF * EDIM + cA] = aA;
                out[bF * EDIM + cB] = aB;
            }
        }
        grid_barrier();

        cur = nxt;
    }
}

// ---------------------------------------------------------------------------
extern "C" void kernel_launch(void* const* d_in, const int* in_sizes, int n_in,
                              void* d_out, int out_size) {
    const float* x    = (const float*)d_in[0];
    const float* W_ih = (const float*)d_in[1];
    const float* W_hh = (const float*)d_in[2];
    const float* b_ih = (const float*)d_in[3];
    const float* b_hh = (const float*)d_in[4];
    const float* W_ya = (const float*)d_in[5];
    const float* b_ya = (const float*)d_in[6];
    const float* W_aa = (const float*)d_in[7];
    const float* b_aa = (const float*)d_in[8];
    float* out = (float*)d_out;

    cudaFuncSetAttribute(rnn_persistent,
                         cudaFuncAttributeMaxDynamicSharedMemorySize, SMEM_BYTES);

    xw_gemm<<<dim3((BATCH * S_LEN) / 64, HDIM / 64), 256>>>(x, W_ih, b_ih, b_hh);
    rnn_persistent<<<G, NT, SMEM_BYTES>>>(W_hh, W_ya, W_aa, b_ya, b_aa, out);
}

// round 6
// speedup vs baseline: 1.6627x; 1.6627x over previous
#include <cuda_runtime.h>
#include <math.h>
#include <stdint.h>
#include <stddef.h>

typedef unsigned long long ull;

// Problem dims
static constexpr int S_LEN = 512;
static constexpr int BATCH = 64;
static constexpr int IDIM  = 256;
static constexpr int HDIM  = 512;
static constexpr int EDIM  = 512;

// Grid: 128 worker CTAs (32 clusters x 4 k-split ranks) + 1 barrier cluster
static constexpr int GW  = 128;
static constexpr int G   = 132;
static constexpr int NT  = 256;   // 8 warps

// smem byte offsets
static constexpr int OFF_BUFH = 0;        // 128 x 64 f        = 32768
static constexpr int OFF_BUFA = 32768;    // 256 x 64 f        = 65536
static constexpr int OFF_WHD  = 98304;    // 128 x 16 ull dup  = 16384
static constexpr int OFF_WAD  = 114688;   // 256 x 16 ull dup  = 32768
static constexpr int OFF_RED  = 147456;   // 8w x 16c x 32bp u = 32768
static constexpr int OFF_MBOX = 180224;   // 4src x 2ph x 4c x 32bp = 8192
static constexpr int SMEM_BYTES = 188416;

// Device scratch (allocation-free rule)
__device__ float g_xw[(size_t)S_LEN * HDIM * BATCH];  // [t][c][b]
__device__ float g_h[2][HDIM * BATCH];                // [c][b] parity buffers
__device__ float g_a[2][EDIM * BATCH];
__device__ int   g_arr[GW];
__device__ int   g_rel;

// ---------------- f32x2 helpers ----------------
__device__ __forceinline__ ull packdup(float w) {
    ull r; unsigned u = __float_as_uint(w);
    asm("mov.b64 %0, {%1, %2};" : "=l"(r) : "r"(u), "r"(u));
    return r;
}
__device__ __forceinline__ ull pack2f(float a, float b) {
    ull r; asm("mov.b64 %0, {%1, %2};" : "=l"(r) : "f"(a), "f"(b));
    return r;
}
__device__ __forceinline__ float2 unpk(ull v) {
    float2 r; asm("mov.b64 {%0, %1}, %2;" : "=f"(r.x), "=f"(r.y) : "l"(v));
    return r;
}
__device__ __forceinline__ ull fma2(ull a, ull b, ull c) {
    ull d; asm("fma.rn.f32x2 %0, %1, %2, %3;" : "=l"(d) : "l"(a), "l"(b), "l"(c));
    return d;
}
__device__ __forceinline__ ull add2(ull a, ull b) {
    ull d; asm("add.rn.f32x2 %0, %1, %2;" : "=l"(d) : "l"(a), "l"(b));
    return d;
}

// ---------------- cluster / DSMEM helpers ----------------
__device__ __forceinline__ unsigned s2u(const void* p) {
    unsigned a;
    asm("{ .reg .u64 t; cvta.to.shared.u64 t, %1; cvt.u32.u64 %0, t; }"
        : "=r"(a) : "l"(p));
    return a;
}
__device__ __forceinline__ void dsmem_st64(unsigned laddr, int rk, ull v) {
    unsigned ra;
    asm volatile("mapa.shared::cluster.u32 %0, %1, %2;" : "=r"(ra) : "r"(laddr), "r"(rk));
    asm volatile("st.shared::cluster.b64 [%0], %1;" :: "r"(ra), "l"(v) : "memory");
}
__device__ __forceinline__ void cluster_sync_() {
    asm volatile("barrier.cluster.arrive.aligned;" ::: "memory");
    asm volatile("barrier.cluster.wait.aligned;" ::: "memory");
}

// ---------------- grid barrier (flag array + dedicated leader) ----------------
__device__ __forceinline__ void worker_barrier(int bid, int v) {
    __syncthreads();
    if (threadIdx.x == 0) {
        __threadfence();
        *(volatile int*)&g_arr[bid] = v;
        while (*(volatile int*)&g_rel != v) { }
        __threadfence();
    }
    __syncthreads();
}

// ---------------------------------------------------------------------------
// Precompute GEMM: g_xw[t][j][b] = sum_i x[b][t][i]*W_ih[j][i] + b_ih[j]+b_hh[j]
// ---------------------------------------------------------------------------
__global__ __launch_bounds__(256) void xw_gemm(const float* __restrict__ x,
                                               const float* __restrict__ W_ih,
                                               const float* __restrict__ b_ih,
                                               const float* __restrict__ b_hh) {
    __shared__ float As[16][68];
    __shared__ float Bs[16][68];

    const int r0 = blockIdx.x * 64;
    const int j0 = blockIdx.y * 64;
    const int tx = threadIdx.x & 15;
    const int ty = threadIdx.x >> 4;

    float acc[4][4] = {};

    for (int k0 = 0; k0 < IDIM; k0 += 16) {
#pragma unroll
        for (int m = 0; m < 4; ++m) {
            int lin = threadIdx.x + 256 * m;
            int rr = lin >> 4, kk = lin & 15;
            As[kk][rr] = x[(size_t)(r0 + rr) * IDIM + k0 + kk];
            Bs[kk][rr] = W_ih[(size_t)(j0 + rr) * IDIM + k0 + kk];
        }
        __syncthreads();
#pragma unroll
        for (int kk = 0; kk < 16; ++kk) {
            float4 av = *(const float4*)&As[kk][ty * 4];
            float4 bv = *(const float4*)&Bs[kk][tx * 4];
            float af[4] = {av.x, av.y, av.z, av.w};
            float bf[4] = {bv.x, bv.y, bv.z, bv.w};
#pragma unroll
            for (int i = 0; i < 4; ++i)
#pragma unroll
                for (int j = 0; j < 4; ++j)
                    acc[i][j] += af[i] * bf[j];
        }
        __syncthreads();
    }

#pragma unroll
    for (int i = 0; i < 4; ++i) {
        int r = r0 + ty * 4 + i;
        int t = r & (S_LEN - 1);
        int b = r >> 9;
#pragma unroll
        for (int j = 0; j < 4; ++j) {
            int col = j0 + tx * 4 + j;
            g_xw[((size_t)t * HDIM + col) * BATCH + b] = acc[i][j] + b_ih[col] + b_hh[col];
        }
    }
}

// ---------------------------------------------------------------------------
// Persistent pipelined RNN kernel.
// Round r (r = 0..S):  h_{r+1} = tanh(xw_r + h_r W_hh^T)        [rounds 0..S-1]
//                      a_r     = tanh(h_r W_ya^T + a_{r-1} W_aa^T + bias)
//                                [rounds 1..S; round 0 stores a_0 = 0]
// Output: a_S at round S.
// ---------------------------------------------------------------------------
__global__ __launch_bounds__(NT, 1) __cluster_dims__(4, 1, 1)
void rnn_all(const float* __restrict__ W_hh,
             const float* __restrict__ W_ya,
             const float* __restrict__ b_ya,
             const float* __restrict__ W_aa,
             const float* __restrict__ b_aa,
             float* __restrict__ out) {
    extern __shared__ char smem[];
    float* bufH = (float*)(smem + OFF_BUFH);
    float* bufA = (float*)(smem + OFF_BUFA);
    ull*   wHd  = (ull*)(smem + OFF_WHD);
    ull*   wAd  = (ull*)(smem + OFF_WAD);
    ull*   red  = (ull*)(smem + OFF_RED);
    ull*   mbox = (ull*)(smem + OFF_MBOX);

    const int tid = threadIdx.x;
    const int bid = blockIdx.x;

    // ---- barrier-leader cluster ----
    if (bid >= GW) {
        if (bid == GW) {
            for (int v = 1; v <= S_LEN + 1; ++v) {
                if (tid < GW) { while (*(volatile int*)&g_arr[tid] != v) { } }
                __syncthreads();
                if (tid == 0) { __threadfence(); *(volatile int*)&g_rel = v; }
                __syncthreads();
            }
        }
        return;
    }

    // ---- worker setup ----
    const int cl = bid >> 2;         // cluster / column-group 0..31
    const int ks = bid & 3;          // k-split rank (cluster rank)
    const int c0 = cl * 16;

    const int w  = tid >> 5;         // warp 0..7
    const int bp = tid & 31;         // batch-pair lane

    // combine roles
    const int phC = tid >> 7;            // 0: h-cols, 1: a-cols
    const int jC  = (tid >> 5) & 3;      // owned col slot 0..3
    const int bpC = tid & 31;
    const int cC  = c0 + ks * 4 + jC;    // owned global column
    const float biasC = (phC == 1) ? (b_ya[cC] + b_aa[cC]) : 0.f;

    // reduce roles
    const int c2R = tid >> 5;            // 0..7 (cols c2R and c2R+8)
    const int bpR = tid & 31;

    const unsigned mbox_u = s2u(mbox);

    // zero-init h_0 (parity 0) and a_{-1} (parity 1; values never used, kept finite)
    for (int i = bid * NT + tid; i < HDIM * BATCH / 2; i += GW * NT) {
        ((ull*)g_h[0])[i] = 0ull;
        ((ull*)g_a[1])[i] = 0ull;
    }

    // resident dup'd weights: wHd[k][c], wAd[k][c]
    for (int i = tid; i < 128 * 16; i += NT) {
        int k = i >> 4, c = i & 15;
        wHd[i] = packdup(__ldg(&W_hh[(size_t)(c0 + c) * HDIM + ks * 128 + k]));
    }
    for (int i = tid; i < 256 * 16; i += NT) {
        int k = i >> 4, c = i & 15;
        float v = (ks < 2) ? __ldg(&W_ya[(size_t)(c0 + c) * HDIM + ks * 256 + k])
                           : __ldg(&W_aa[(size_t)(c0 + c) * EDIM + (ks - 2) * 256 + k]);
        wAd[i] = packdup(v);
    }

    worker_barrier(bid, 1);

    for (int r = 0; r <= S_LEN; ++r) {
        const int p = r & 1;

        // prefetch xw for combine (rounds 0..S-1 only)
        ull xwv = 0ull;
        if (phC == 0 && r < S_LEN)
            xwv = *(const ull*)(g_xw + ((size_t)r * HDIM + cC) * BATCH + 2 * bpC);

        // ---- per-warp self-staging (k-slices this warp consumes) ----
        {
            const float4* srcH = (const float4*)(g_h[p] + (ks * 128 + w * 16) * BATCH);
            float4* dstH = (float4*)(bufH + w * 16 * BATCH);
#pragma unroll
            for (int q = 0; q < 8; ++q) dstH[q * 32 + bp] = __ldcg(&srcH[q * 32 + bp]);

            const float* sA = (ks < 2) ? (g_h[p] + (ks * 256 + w * 32) * BATCH)
                                       : (g_a[p ^ 1] + ((ks - 2) * 256 + w * 32) * BATCH);
            const float4* srcA = (const float4*)sA;
            float4* dstA = (float4*)(bufA + w * 32 * BATCH);
#pragma unroll
            for (int q = 0; q < 16; ++q) dstA[q * 32 + bp] = __ldcg(&srcA[q * 32 + bp]);
        }
        __syncwarp();

        // ---- h-GEMM: 16 cols x 16 k (this warp) x 32 b-pairs ----
        {
            ull acc[16];
#pragma unroll
            for (int c = 0; c < 16; ++c) acc[c] = 0ull;
            const float* bh = bufH + w * 16 * BATCH;
            const ull*  whr = wHd + w * 16 * 16;
#pragma unroll 4
            for (int kk = 0; kk < 16; ++kk) {
                ull hv = *(const ull*)(bh + kk * BATCH + bp * 2);
                const ulonglong2* wp = (const ulonglong2*)(whr + kk * 16);
#pragma unroll
                for (int cp = 0; cp < 8; ++cp) {
                    ulonglong2 w2 = wp[cp];
                    acc[2 * cp]     = fma2(hv, w2.x, acc[2 * cp]);
                    acc[2 * cp + 1] = fma2(hv, w2.y, acc[2 * cp + 1]);
                }
            }
#pragma unroll
            for (int c = 0; c < 16; ++c) red[(w * 16 + c) * 32 + bp] = acc[c];
        }

        // ---- a-GEMM: 16 cols x 32 k (this warp), accs stay in regs ----
        ull accA[16];
        {
#pragma unroll
            for (int c = 0; c < 16; ++c) accA[c] = 0ull;
            const float* ba = bufA + w * 32 * BATCH;
            const ull*  war = wAd + w * 32 * 16;
#pragma unroll 4
            for (int kk = 0; kk < 32; ++kk) {
                ull hv = *(const ull*)(ba + kk * BATCH + bp * 2);
                const ulonglong2* wp = (const ulonglong2*)(war + kk * 16);
#pragma unroll
                for (int cp = 0; cp < 8; ++cp) {
                    ulonglong2 w2 = wp[cp];
                    accA[2 * cp]     = fma2(hv, w2.x, accA[2 * cp]);
                    accA[2 * cp + 1] = fma2(hv, w2.y, accA[2 * cp + 1]);
                }
            }
        }
        __syncthreads();

        // ---- h-reduce over 8 warps + DSMEM scatter to owners ----
#pragma unroll
        for (int i = 0; i < 2; ++i) {
            int cc = c2R + i * 8;
            ull s = red[cc * 32 + bpR];
#pragma unroll
            for (int ww = 1; ww < 8; ++ww) s = add2(s, red[(ww * 16 + cc) * 32 + bpR]);
            unsigned la = mbox_u + ((((ks * 2 + 0) * 4 + (cc & 3)) * 32 + bpR) << 3);
            dsmem_st64(la, cc >> 2, s);
        }
        __syncthreads();   // red reads done -> safe to overwrite

        // ---- a-accs to red, reduce, scatter ----
#pragma unroll
        for (int c = 0; c < 16; ++c) red[(w * 16 + c) * 32 + bp] = accA[c];
        __syncthreads();
#pragma unroll
        for (int i = 0; i < 2; ++i) {
            int cc = c2R + i * 8;
            ull s = red[cc * 32 + bpR];
#pragma unroll
            for (int ww = 1; ww < 8; ++ww) s = add2(s, red[(ww * 16 + cc) * 32 + bpR]);
            unsigned la = mbox_u + ((((ks * 2 + 1) * 4 + (cc & 3)) * 32 + bpR) << 3);
            dsmem_st64(la, cc >> 2, s);
        }

        cluster_sync_();   // all mailbox slices delivered cluster-wide

        // ---- combine: sum 4 k-split partials, activate, publish ----
        {
            ull v = mbox[((0 * 2 + phC) * 4 + jC) * 32 + bpC];
            v = add2(v, mbox[((1 * 2 + phC) * 4 + jC) * 32 + bpC]);
            v = add2(v, mbox[((2 * 2 + phC) * 4 + jC) * 32 + bpC]);
            v = add2(v, mbox[((3 * 2 + phC) * 4 + jC) * 32 + bpC]);
            if (phC == 0) {
                if (r < S_LEN) {
                    v = add2(v, xwv);
                    float2 f = unpk(v);
                    f.x = tanhf(f.x); f.y = tanhf(f.y);
                    *(ull*)(g_h[p ^ 1] + cC * BATCH + 2 * bpC) = pack2f(f.x, f.y);
                }
            } else {
                float2 f;
                if (r == 0) {
                    f.x = 0.f; f.y = 0.f;          // a_0 = initial state (exact zero)
                } else {
                    f = unpk(v);
                    f.x = tanhf(f.x + biasC); f.y = tanhf(f.y + biasC);
                }
                *(ull*)(g_a[p] + cC * BATCH + 2 * bpC) = pack2f(f.x, f.y);
                if (r == S_LEN) {
                    out[(size_t)(2 * bpC) * EDIM + cC]     = f.x;
                    out[(size_t)(2 * bpC + 1) * EDIM + cC] = f.y;
                }
            }
        }

        if (r < S_LEN) worker_barrier(bid, r + 2);
    }
}

// ---------------------------------------------------------------------------
extern "C" void kernel_launch(void* const* d_in, const int* in_sizes, int n_in,
                              void* d_out, int out_size) {
    const float* x    = (const float*)d_in[0];
    const float* W_ih = (const float*)d_in[1];
    const float* W_hh = (const float*)d_in[2];
    const float* b_ih = (const float*)d_in[3];
    const float* b_hh = (const float*)d_in[4];
    const float* W_ya = (const float*)d_in[5];
    const float* b_ya = (const float*)d_in[6];
    const float* W_aa = (const float*)d_in[7];
    const float* b_aa = (const float*)d_in[8];
    float* out = (float*)d_out;

    cudaFuncSetAttribute(rnn_all,
                         cudaFuncAttributeMaxDynamicSharedMemorySize, SMEM_BYTES);

    xw_gemm<<<dim3((BATCH * S_LEN) / 64, HDIM / 64), 256>>>(x, W_ih, b_ih, b_hh);
    rnn_all<<<G, NT, SMEM_BYTES>>>(W_hh, W_ya, b_ya, W_aa, b_aa, out);
}

// round 7
// speedup vs baseline: 1.7115x; 1.0293x over previous
#include <cuda_runtime.h>
#include <math.h>
#include <stdint.h>
#include <stddef.h>

typedef unsigned long long ull;

// Problem dims
static constexpr int S_LEN = 512;
static constexpr int BATCH = 64;
static constexpr int IDIM  = 256;
static constexpr int HDIM  = 512;
static constexpr int EDIM  = 512;

// Grid: 128 worker CTAs (32 clusters x 4 k-split ranks) + 1 barrier cluster
static constexpr int GW  = 128;
static constexpr int G   = 132;
static constexpr int NT  = 512;   // 16 warps -> 4 warps per SMSP

// smem byte offsets
static constexpr int OFF_WHD  = 0;        // 128k x 16c ull dup = 16384
static constexpr int OFF_WAD  = 16384;    // 256k x 16c ull dup = 32768
static constexpr int OFF_RED  = 49152;    // 16w x 16c x 32bp ull = 65536
static constexpr int OFF_MBOX = 114688;   // 4src x 2ph x 4c x 32bp ull = 8192
static constexpr int SMEM_BYTES = 122880;

// Device scratch (allocation-free rule)
__device__ float g_xw[(size_t)S_LEN * HDIM * BATCH];  // [t][c][b]
__device__ float g_h[2][HDIM * BATCH];                // [c][b] parity buffers
__device__ float g_a[2][EDIM * BATCH];
__device__ int   g_arr[GW];
__device__ int   g_rel;

// ---------------- f32x2 helpers ----------------
__device__ __forceinline__ ull packdup(float w) {
    ull r; unsigned u = __float_as_uint(w);
    asm("mov.b64 %0, {%1, %2};" : "=l"(r) : "r"(u), "r"(u));
    return r;
}
__device__ __forceinline__ ull pack2f(float a, float b) {
    ull r; asm("mov.b64 %0, {%1, %2};" : "=l"(r) : "f"(a), "f"(b));
    return r;
}
__device__ __forceinline__ float2 unpk(ull v) {
    float2 r; asm("mov.b64 {%0, %1}, %2;" : "=f"(r.x), "=f"(r.y) : "l"(v));
    return r;
}
__device__ __forceinline__ ull fma2(ull a, ull b, ull c) {
    ull d; asm("fma.rn.f32x2 %0, %1, %2, %3;" : "=l"(d) : "l"(a), "l"(b), "l"(c));
    return d;
}
__device__ __forceinline__ ull add2(ull a, ull b) {
    ull d; asm("add.rn.f32x2 %0, %1, %2;" : "=l"(d) : "l"(a), "l"(b));
    return d;
}

// ---------------- cluster / DSMEM helpers ----------------
__device__ __forceinline__ unsigned s2u(const void* p) {
    unsigned a;
    asm("{ .reg .u64 t; cvta.to.shared.u64 t, %1; cvt.u32.u64 %0, t; }"
        : "=r"(a) : "l"(p));
    return a;
}
__device__ __forceinline__ void dsmem_st64(unsigned laddr, int rk, ull v) {
    unsigned ra;
    asm volatile("mapa.shared::cluster.u32 %0, %1, %2;" : "=r"(ra) : "r"(laddr), "r"(rk));
    asm volatile("st.shared::cluster.b64 [%0], %1;" :: "r"(ra), "l"(v) : "memory");
}
__device__ __forceinline__ void cluster_sync_() {
    asm volatile("barrier.cluster.arrive.aligned;" ::: "memory");
    asm volatile("barrier.cluster.wait.aligned;" ::: "memory");
}

// ---------------- grid barrier (flag array + dedicated leader CTA) ----------------
__device__ __forceinline__ void worker_barrier(int bid, int v) {
    __syncthreads();
    if (threadIdx.x == 0) {
        __threadfence();
        *(volatile int*)&g_arr[bid] = v;
        while (*(volatile int*)&g_rel != v) { }
        __threadfence();
    }
    __syncthreads();
}

// ---------------------------------------------------------------------------
// Precompute GEMM: g_xw[t][j][b] = sum_i x[b][t][i]*W_ih[j][i] + b_ih[j]+b_hh[j]
// ---------------------------------------------------------------------------
__global__ __launch_bounds__(256) void xw_gemm(const float* __restrict__ x,
                                               const float* __restrict__ W_ih,
                                               const float* __restrict__ b_ih,
                                               const float* __restrict__ b_hh) {
    __shared__ float As[16][68];
    __shared__ float Bs[16][68];

    const int r0 = blockIdx.x * 64;
    const int j0 = blockIdx.y * 64;
    const int tx = threadIdx.x & 15;
    const int ty = threadIdx.x >> 4;

    float acc[4][4] = {};

    for (int k0 = 0; k0 < IDIM; k0 += 16) {
#pragma unroll
        for (int m = 0; m < 4; ++m) {
            int lin = threadIdx.x + 256 * m;
            int rr = lin >> 4, kk = lin & 15;
            As[kk][rr] = x[(size_t)(r0 + rr) * IDIM + k0 + kk];
            Bs[kk][rr] = W_ih[(size_t)(j0 + rr) * IDIM + k0 + kk];
        }
        __syncthreads();
#pragma unroll
        for (int kk = 0; kk < 16; ++kk) {
            float4 av = *(const float4*)&As[kk][ty * 4];
            float4 bv = *(const float4*)&Bs[kk][tx * 4];
            float af[4] = {av.x, av.y, av.z, av.w};
            float bf[4] = {bv.x, bv.y, bv.z, bv.w};
#pragma unroll
            for (int i = 0; i < 4; ++i)
#pragma unroll
                for (int j = 0; j < 4; ++j)
                    acc[i][j] += af[i] * bf[j];
        }
        __syncthreads();
    }

#pragma unroll
    for (int i = 0; i < 4; ++i) {
        int r = r0 + ty * 4 + i;
        int t = r & (S_LEN - 1);
        int b = r >> 9;
#pragma unroll
        for (int j = 0; j < 4; ++j) {
            int col = j0 + tx * 4 + j;
            g_xw[((size_t)t * HDIM + col) * BATCH + b] = acc[i][j] + b_ih[col] + b_hh[col];
        }
    }
}

// ---------------------------------------------------------------------------
// Persistent pipelined RNN kernel.
// Round r (r = 0..S):  h_{r+1} = tanh(xw_r + h_r W_hh^T)        [rounds 0..S-1]
//                      a_r     = tanh(h_r W_ya^T + a_{r-1} W_aa^T + bias)
//                                [rounds 1..S; round 0 stores a_0 = 0]
// Output: a_S at round S.
// ---------------------------------------------------------------------------
__global__ __launch_bounds__(NT, 1) __cluster_dims__(4, 1, 1)
void rnn_all(const float* __restrict__ W_hh,
             const float* __restrict__ W_ya,
             const float* __restrict__ b_ya,
             const float* __restrict__ W_aa,
             const float* __restrict__ b_aa,
             float* __restrict__ out) {
    extern __shared__ char smem[];
    ull* wHd  = (ull*)(smem + OFF_WHD);
    ull* wAd  = (ull*)(smem + OFF_WAD);
    ull* red  = (ull*)(smem + OFF_RED);
    ull* mbox = (ull*)(smem + OFF_MBOX);

    const int tid = threadIdx.x;
    const int bid = blockIdx.x;

    // ---- barrier-leader cluster ----
    if (bid >= GW) {
        if (bid == GW) {
            for (int v = 1; v <= S_LEN + 1; ++v) {
                if (tid < GW) { while (*(volatile int*)&g_arr[tid] != v) { } }
                __syncthreads();
                if (tid == 0) { __threadfence(); *(volatile int*)&g_rel = v; }
                __syncthreads();
            }
        }
        return;
    }

    // ---- worker setup ----
    const int cl = bid >> 2;         // cluster / column-group 0..31
    const int ks = bid & 3;          // k-split rank (cluster rank)
    const int c0 = cl * 16;

    const int w  = tid >> 5;         // warp 0..15
    const int bp = tid & 31;         // batch-pair lane

    // combine roles (first 256 threads)
    const int phC = (tid >> 7) & 1;      // 0: h-cols, 1: a-cols
    const int jC  = (tid >> 5) & 3;      // owned col slot 0..3
    const int bpC = tid & 31;
    const int cC  = c0 + ks * 4 + jC;    // owned global column
    const float biasC = (tid < 256 && phC == 1) ? (b_ya[cC] + b_aa[cC]) : 0.f;

    // reduce roles: one (col, bp) per thread
    const int ccR = tid >> 5;            // 0..15
    const int bpR = tid & 31;

    const unsigned mbox_u = s2u(mbox);

    // zero-init h_0 (parity 0) and a_{-1} (parity 1; never used numerically)
    for (int i = bid * NT + tid; i < HDIM * BATCH / 2; i += GW * NT) {
        ((ull*)g_h[0])[i] = 0ull;
        ((ull*)g_a[1])[i] = 0ull;
    }

    // resident dup'd weights: wHd[k][c], wAd[k][c]
    for (int i = tid; i < 128 * 16; i += NT) {
        int k = i >> 4, c = i & 15;
        wHd[i] = packdup(__ldg(&W_hh[(size_t)(c0 + c) * HDIM + ks * 128 + k]));
    }
    for (int i = tid; i < 256 * 16; i += NT) {
        int k = i >> 4, c = i & 15;
        float v = (ks < 2) ? __ldg(&W_ya[(size_t)(c0 + c) * HDIM + ks * 256 + k])
                           : __ldg(&W_aa[(size_t)(c0 + c) * EDIM + (ks - 2) * 256 + k]);
        wAd[i] = packdup(v);
    }

    worker_barrier(bid, 1);

    for (int r = 0; r <= S_LEN; ++r) {
        const int p = r & 1;

        // prefetch xw for combine (rounds 0..S-1 only)
        ull xwv = 0ull;
        if (tid < 256 && phC == 0 && r < S_LEN)
            xwv = __ldcg((const ull*)(g_xw + ((size_t)r * HDIM + cC) * BATCH) + bpC);

        // ---- h-GEMM: 16 cols x 8 k (this warp) x 32 b-pairs, A from L2 ----
        {
            ull acc[16];
#pragma unroll
            for (int c = 0; c < 16; ++c) acc[c] = 0ull;
            const ull* hsrc = (const ull*)(g_h[p] + (ks * 128 + w * 8) * BATCH) + bp;
            const ull* whr  = wHd + (w * 8) * 16;
#pragma unroll
            for (int kk = 0; kk < 8; ++kk) {
                ull hv = __ldcg(hsrc + kk * 32);
                const ulonglong2* wp = (const ulonglong2*)(whr + kk * 16);
#pragma unroll
                for (int cp = 0; cp < 8; ++cp) {
                    ulonglong2 w2 = wp[cp];
                    acc[2 * cp]     = fma2(hv, w2.x, acc[2 * cp]);
                    acc[2 * cp + 1] = fma2(hv, w2.y, acc[2 * cp + 1]);
                }
            }
#pragma unroll
            for (int c = 0; c < 16; ++c) red[(w * 16 + c) * 32 + bp] = acc[c];
        }

        // ---- a-GEMM: 16 cols x 16 k (this warp), accs stay in regs ----
        ull accA[16];
        {
#pragma unroll
            for (int c = 0; c < 16; ++c) accA[c] = 0ull;
            const float* sA = (ks < 2) ? (g_h[p] + (ks * 256 + w * 16) * BATCH)
                                       : (g_a[p ^ 1] + ((ks - 2) * 256 + w * 16) * BATCH);
            const ull* asrc = (const ull*)sA + bp;
            const ull* war  = wAd + (w * 16) * 16;
#pragma unroll
            for (int kk = 0; kk < 16; ++kk) {
                ull hv = __ldcg(asrc + kk * 32);
                const ulonglong2* wp = (const ulonglong2*)(war + kk * 16);
#pragma unroll
                for (int cp = 0; cp < 8; ++cp) {
                    ulonglong2 w2 = wp[cp];
                    accA[2 * cp]     = fma2(hv, w2.x, accA[2 * cp]);
                    accA[2 * cp + 1] = fma2(hv, w2.y, accA[2 * cp + 1]);
                }
            }
        }
        __syncthreads();

        // ---- h-reduce over 16 warps + DSMEM scatter to owner CTAs ----
        {
            ull s = red[ccR * 32 + bpR];
#pragma unroll
            for (int ww = 1; ww < 16; ++ww) s = add2(s, red[(ww * 16 + ccR) * 32 + bpR]);
            unsigned la = mbox_u + ((((ks * 2 + 0) * 4 + (ccR & 3)) * 32 + bpR) << 3);
            dsmem_st64(la, ccR >> 2, s);
        }
        __syncthreads();   // red reads done -> safe to overwrite

        // ---- a-accs to red, reduce, scatter ----
#pragma unroll
        for (int c = 0; c < 16; ++c) red[(w * 16 + c) * 32 + bp] = accA[c];
        __syncthreads();
        {
            ull s = red[ccR * 32 + bpR];
#pragma unroll
            for (int ww = 1; ww < 16; ++ww) s = add2(s, red[(ww * 16 + ccR) * 32 + bpR]);
            unsigned la = mbox_u + ((((ks * 2 + 1) * 4 + (ccR & 3)) * 32 + bpR) << 3);
            dsmem_st64(la, ccR >> 2, s);
        }

        cluster_sync_();   // all mailbox slices delivered cluster-wide

        // ---- combine: sum 4 k-split partials, activate, publish ----
        if (tid < 256) {
            ull v = mbox[((0 * 2 + phC) * 4 + jC) * 32 + bpC];
            v = add2(v, mbox[((1 * 2 + phC) * 4 + jC) * 32 + bpC]);
            v = add2(v, mbox[((2 * 2 + phC) * 4 + jC) * 32 + bpC]);
            v = add2(v, mbox[((3 * 2 + phC) * 4 + jC) * 32 + bpC]);
            if (phC == 0) {
                if (r < S_LEN) {
                    v = add2(v, xwv);
                    float2 f = unpk(v);
                    f.x = tanhf(f.x); f.y = tanhf(f.y);
                    *(ull*)(g_h[p ^ 1] + cC * BATCH + 2 * bpC) = pack2f(f.x, f.y);
                }
            } else {
                float2 f;
                if (r == 0) {
                    f.x = 0.f; f.y = 0.f;          // a_0 = initial state (exact zero)
                } else {
                    f = unpk(v);
                    f.x = tanhf(f.x + biasC); f.y = tanhf(f.y + biasC);
                }
                *(ull*)(g_a[p] + cC * BATCH + 2 * bpC) = pack2f(f.x, f.y);
                if (r == S_LEN) {
                    out[(size_t)(2 * bpC) * EDIM + cC]     = f.x;
                    out[(size_t)(2 * bpC + 1) * EDIM + cC] = f.y;
                }
            }
        }

        if (r < S_LEN) worker_barrier(bid, r + 2);
    }
}

// ---------------------------------------------------------------------------
extern "C" void kernel_launch(void* const* d_in, const int* in_sizes, int n_in,
                              void* d_out, int out_size) {
    const float* x    = (const float*)d_in[0];
    const float* W_ih = (const float*)d_in[1];
    const float* W_hh = (const float*)d_in[2];
    const float* b_ih = (const float*)d_in[3];
    const float* b_hh = (const float*)d_in[4];
    const float* W_ya = (const float*)d_in[5];
    const float* b_ya = (const float*)d_in[6];
    const float* W_aa = (const float*)d_in[7];
    const float* b_aa = (const float*)d_in[8];
    float* out = (float*)d_out;

    cudaFuncSetAttribute(rnn_all,
                         cudaFuncAttributeMaxDynamicSharedMemorySize, SMEM_BYTES);

    xw_gemm<<<dim3((BATCH * S_LEN) / 64, HDIM / 64), 256>>>(x, W_ih, b_ih, b_hh);
    rnn_all<<<G, NT, SMEM_BYTES>>>(W_hh, W_ya, b_ya, W_aa, b_aa, out);
}